// round 4
// baseline (speedup 1.0000x reference)
#include <cuda_runtime.h>
#include <cuda_bf16.h>
#include <math.h>

#define N_NODES 100000
#define N_EDGES 400000
#define N_GRAPHS 2500
#define DIM 128
#define F_IN 78
#define BN_EPS 1e-5f

// ---------------- scratch (device globals; no allocation) ----------------
__device__ float g_t0[N_NODES * DIM];
__device__ float g_t1[N_NODES * DIM];
__device__ float g_g1[N_NODES * DIM];
__device__ float g_g2[N_NODES * DIM];
__device__ float g_z1[N_NODES * DIM];
__device__ float g_z2[N_NODES * DIM];
__device__ float g_z3[N_NODES * DIM];

__device__ int   g_cnt[N_NODES];
__device__ float g_dis[N_NODES];
__device__ int   g_rowptr[N_NODES + 1];
__device__ int   g_cursor[N_NODES];
__device__ int   g_csrc[N_EDGES];
__device__ int   g_blksums[256];
__device__ float g_sum[3 * DIM], g_sumsq[3 * DIM];
__device__ float g_a[3 * DIM], g_b[3 * DIM];
__device__ int   g_gstart[N_GRAPHS + 1];

// ---------------- init / CSR build ----------------
__global__ void k_init() {
    int i = blockIdx.x * blockDim.x + threadIdx.x;
    if (i < N_NODES) g_cnt[i] = 0;
    if (i < 3 * DIM) { g_sum[i] = 0.f; g_sumsq[i] = 0.f; }
}

__global__ void k_hist(const int* __restrict__ dst) {
    int e = blockIdx.x * blockDim.x + threadIdx.x;
    if (e < N_EDGES) atomicAdd(&g_cnt[dst[e]], 1);
}

__global__ void k_dis() {
    int i = blockIdx.x * blockDim.x + threadIdx.x;
    if (i < N_NODES) g_dis[i] = rsqrtf((float)(g_cnt[i] + 1));
}

__global__ void k_scan1() {
    __shared__ int s[1024];
    int tid = threadIdx.x;
    int i = blockIdx.x * 1024 + tid;
    int v = (i < N_NODES) ? g_cnt[i] : 0;
    s[tid] = v;
    __syncthreads();
    for (int off = 1; off < 1024; off <<= 1) {
        int t = (tid >= off) ? s[tid - off] : 0;
        __syncthreads();
        s[tid] += t;
        __syncthreads();
    }
    if (i < N_NODES) g_cursor[i] = s[tid];
    if (tid == 1023) g_blksums[blockIdx.x] = s[1023];
}

__global__ void k_scan2(int nblocks) {
    if (threadIdx.x == 0 && blockIdx.x == 0) {
        int run = 0;
        for (int b = 0; b < nblocks; b++) {
            int t = g_blksums[b];
            g_blksums[b] = run;
            run += t;
        }
    }
}

__global__ void k_scan3() {
    int i = blockIdx.x * blockDim.x + threadIdx.x;
    if (i < N_NODES) {
        int val = g_cursor[i] + g_blksums[i >> 10];
        g_rowptr[i + 1] = val;
        g_cursor[i] = val - g_cnt[i];
        if (i == 0) g_rowptr[0] = 0;
    }
}

__global__ void k_scatter(const int* __restrict__ src, const int* __restrict__ dst) {
    int e = blockIdx.x * blockDim.x + threadIdx.x;
    if (e < N_EDGES) {
        int d = dst[e];
        int pos = atomicAdd(&g_cursor[d], 1);
        g_csrc[pos] = src[e];
    }
}

__global__ void k_gstart(const int* __restrict__ batch) {
    int g = blockIdx.x * blockDim.x + threadIdx.x;
    if (g <= N_GRAPHS) {
        int lo = 0, hi = N_NODES;
        while (lo < hi) {
            int mid = (lo + hi) >> 1;
            if (batch[mid] < g) lo = mid + 1; else hi = mid;
        }
        g_gstart[g] = lo;
    }
}

// ---------------- tf32 helpers ----------------
__device__ __forceinline__ unsigned to_tf32(float x) {
    unsigned r;
    asm("cvt.rna.tf32.f32 %0, %1;" : "=r"(r) : "f"(x));
    return r;
}
__device__ __forceinline__ void split_tf32(float x, unsigned& hi, unsigned& lo) {
    hi = to_tf32(x);
    float hif = __uint_as_float(hi);
    lo = to_tf32(x - hif);
}
__device__ __forceinline__ void mma_tf32(float d[4],
                                         unsigned a0, unsigned a1, unsigned a2, unsigned a3,
                                         unsigned b0, unsigned b1) {
    asm volatile(
        "mma.sync.aligned.m16n8k8.row.col.f32.tf32.tf32.f32 "
        "{%0,%1,%2,%3}, {%4,%5,%6,%7}, {%8,%9}, {%0,%1,%2,%3};"
        : "+f"(d[0]), "+f"(d[1]), "+f"(d[2]), "+f"(d[3])
        : "r"(a0), "r"(a1), "r"(a2), "r"(a3), "r"(b0), "r"(b1));
}

// ---------------- tensor-core GEMM: C[100000 x 128] = A[. x K] @ W[K x 128] ----------------
// CTA tile 128x128, 256 threads (8 warps), warp tile m64 x n32 (4x4 m16n8k8),
// tf32 hi/lo split (3 MMAs) for ~fp32 accuracy.
#define TMM 128
#define KC 32
#define ASTRIDE 36
#define BSTRIDE 132
// dynamic smem layout (uint words): AH[128*36] AL[128*36] BH[32*132] BL[32*132] SredS[128] SredQ[128]
#define SM_AH 0
#define SM_AL (SM_AH + TMM * ASTRIDE)
#define SM_BH (SM_AL + TMM * ASTRIDE)
#define SM_BL (SM_BH + KC * BSTRIDE)
#define SM_SS (SM_BL + KC * BSTRIDE)
#define SM_SQ (SM_SS + 128)
#define SMEM_WORDS (SM_SQ + 128)

template <int K, bool BIAS, bool RELU, int STATS>
__global__ void __launch_bounds__(256) k_gemm_mma(const float* __restrict__ A,
                                                  const float* __restrict__ W,
                                                  const float* __restrict__ bias,
                                                  float* __restrict__ C) {
    extern __shared__ unsigned smem[];
    unsigned* AH = smem + SM_AH;
    unsigned* AL = smem + SM_AL;
    unsigned* BH = smem + SM_BH;
    unsigned* BL = smem + SM_BL;
    float* SredS = (float*)(smem + SM_SS);
    float* SredQ = (float*)(smem + SM_SQ);

    const int tid = threadIdx.x;
    const int w = tid >> 5;
    const int lane = tid & 31;
    const int g = lane >> 2;
    const int tg = lane & 3;
    const int mwarp = (w >> 2) * 64;   // 0 or 64
    const int nwarp = (w & 3) * 32;    // 0,32,64,96
    const int row0 = blockIdx.x * TMM;

    if (STATS >= 0 && tid < 128) { SredS[tid] = 0.f; SredQ[tid] = 0.f; }

    float acc[4][4][4];
#pragma unroll
    for (int mt = 0; mt < 4; mt++)
#pragma unroll
        for (int nt = 0; nt < 4; nt++)
#pragma unroll
            for (int j = 0; j < 4; j++) acc[mt][nt][j] = 0.f;

    constexpr int KSTEPS = (K + KC - 1) / KC;
    for (int s = 0; s < KSTEPS; s++) {
        const int kk = s * KC;
        // ---- fill A tile (128 x 32) with hi/lo split ----
        if constexpr (K % KC == 0) {
#pragma unroll
            for (int t = 0; t < 4; t++) {
                int idx = tid + t * 256;          // 1024 float4
                int r = idx >> 3, c4 = idx & 7;
                float4 v = make_float4(0.f, 0.f, 0.f, 0.f);
                int grow = row0 + r;
                if (grow < N_NODES) v = *(const float4*)&A[grow * K + kk + c4 * 4];
                unsigned h0, l0, h1, l1, h2, l2, h3, l3;
                split_tf32(v.x, h0, l0); split_tf32(v.y, h1, l1);
                split_tf32(v.z, h2, l2); split_tf32(v.w, h3, l3);
                int base = r * ASTRIDE + c4 * 4;
                AH[base + 0] = h0; AH[base + 1] = h1; AH[base + 2] = h2; AH[base + 3] = h3;
                AL[base + 0] = l0; AL[base + 1] = l1; AL[base + 2] = l2; AL[base + 3] = l3;
            }
        } else {
#pragma unroll
            for (int t = 0; t < 16; t++) {
                int idx = tid + t * 256;          // 4096 scalars
                int r = idx >> 5, c = idx & 31;
                int grow = row0 + r, gcol = kk + c;
                float v = 0.f;
                if (grow < N_NODES && gcol < K) v = A[grow * K + gcol];
                unsigned h, l;
                split_tf32(v, h, l);
                AH[r * ASTRIDE + c] = h;
                AL[r * ASTRIDE + c] = l;
            }
        }
        // ---- fill B tile (32 x 128) with hi/lo split ----
#pragma unroll
        for (int t = 0; t < 4; t++) {
            int idx = tid + t * 256;              // 1024 float4
            int k = idx >> 5, c4 = idx & 31;
            int gk = kk + k;
            float4 v = make_float4(0.f, 0.f, 0.f, 0.f);
            if (gk < K) v = *(const float4*)&W[gk * DIM + c4 * 4];
            unsigned h0, l0, h1, l1, h2, l2, h3, l3;
            split_tf32(v.x, h0, l0); split_tf32(v.y, h1, l1);
            split_tf32(v.z, h2, l2); split_tf32(v.w, h3, l3);
            int base = k * BSTRIDE + c4 * 4;
            BH[base + 0] = h0; BH[base + 1] = h1; BH[base + 2] = h2; BH[base + 3] = h3;
            BL[base + 0] = l0; BL[base + 1] = l1; BL[base + 2] = l2; BL[base + 3] = l3;
        }
        __syncthreads();

        // ---- MMA over 4 k-steps of 8 ----
#pragma unroll
        for (int ks = 0; ks < 4; ks++) {
            const int k0 = ks * 8;
            unsigned ah[4][4], al[4][4];
#pragma unroll
            for (int mt = 0; mt < 4; mt++) {
                int b0 = (mwarp + mt * 16 + g) * ASTRIDE + k0 + tg;
                int b1 = (mwarp + mt * 16 + g + 8) * ASTRIDE + k0 + tg;
                ah[mt][0] = AH[b0]; ah[mt][1] = AH[b1];
                ah[mt][2] = AH[b0 + 4]; ah[mt][3] = AH[b1 + 4];
                al[mt][0] = AL[b0]; al[mt][1] = AL[b1];
                al[mt][2] = AL[b0 + 4]; al[mt][3] = AL[b1 + 4];
            }
#pragma unroll
            for (int nt = 0; nt < 4; nt++) {
                int ncol = nwarp + nt * 8 + g;
                int bb0 = (k0 + tg) * BSTRIDE + ncol;
                int bb1 = (k0 + tg + 4) * BSTRIDE + ncol;
                unsigned bh0 = BH[bb0], bh1 = BH[bb1];
                unsigned bl0 = BL[bb0], bl1 = BL[bb1];
#pragma unroll
                for (int mt = 0; mt < 4; mt++) {
                    mma_tf32(acc[mt][nt], ah[mt][0], ah[mt][1], ah[mt][2], ah[mt][3], bh0, bh1);
                    mma_tf32(acc[mt][nt], ah[mt][0], ah[mt][1], ah[mt][2], ah[mt][3], bl0, bl1);
                    mma_tf32(acc[mt][nt], al[mt][0], al[mt][1], al[mt][2], al[mt][3], bh0, bh1);
                }
            }
        }
        __syncthreads();
    }

    // ---- epilogue ----
#pragma unroll
    for (int nt = 0; nt < 4; nt++) {
        int c0 = nwarp + nt * 8 + 2 * tg;
        float b0 = BIAS ? bias[c0] : 0.f;
        float b1 = BIAS ? bias[c0 + 1] : 0.f;
        float s0 = 0.f, s1 = 0.f, q0 = 0.f, q1 = 0.f;
#pragma unroll
        for (int mt = 0; mt < 4; mt++) {
            int r0 = row0 + mwarp + mt * 16 + g;
            int r1 = r0 + 8;
            float d0 = acc[mt][nt][0] + b0;
            float d1 = acc[mt][nt][1] + b1;
            float d2 = acc[mt][nt][2] + b0;
            float d3 = acc[mt][nt][3] + b1;
            if (RELU) {
                d0 = fmaxf(d0, 0.f); d1 = fmaxf(d1, 0.f);
                d2 = fmaxf(d2, 0.f); d3 = fmaxf(d3, 0.f);
            }
            if (r0 < N_NODES) {
                *(float2*)&C[r0 * DIM + c0] = make_float2(d0, d1);
                if (STATS >= 0) { s0 += d0; s1 += d1; q0 += d0 * d0; q1 += d1 * d1; }
            }
            if (r1 < N_NODES) {
                *(float2*)&C[r1 * DIM + c0] = make_float2(d2, d3);
                if (STATS >= 0) { s0 += d2; s1 += d3; q0 += d2 * d2; q1 += d3 * d3; }
            }
        }
        if (STATS >= 0) {
            atomicAdd(&SredS[c0], s0); atomicAdd(&SredS[c0 + 1], s1);
            atomicAdd(&SredQ[c0], q0); atomicAdd(&SredQ[c0 + 1], q1);
        }
    }

    if constexpr (STATS >= 0) {
        __syncthreads();
        if (tid < 128) {
            atomicAdd(&g_sum[STATS * DIM + tid], SredS[tid]);
            atomicAdd(&g_sumsq[STATS * DIM + tid], SredQ[tid]);
        }
    }
}

// ---------------- BN finalize: fold into affine h = a*z + b ----------------
__global__ void k_bn_final(int layer, const float* __restrict__ gamma,
                           const float* __restrict__ beta) {
    int c = threadIdx.x;
    if (c < DIM) {
        float mu = g_sum[layer * DIM + c] * (1.f / N_NODES);
        float var = g_sumsq[layer * DIM + c] * (1.f / N_NODES) - mu * mu;
        float istd = rsqrtf(var + BN_EPS);
        float a = istd * gamma[c];
        g_a[layer * DIM + c] = a;
        g_b[layer * DIM + c] = beta[c] - mu * a;
    }
}

// ---------------- GCN aggregation ----------------
__global__ void k_gcn_agg(const float* __restrict__ h, const float* __restrict__ bias,
                          float* __restrict__ out) {
    int gt = blockIdx.x * blockDim.x + threadIdx.x;
    int node = gt >> 5;
    int lane = gt & 31;
    if (node >= N_NODES) return;
    float dn = g_dis[node];
    float4 acc = *(const float4*)&h[node * DIM + lane * 4];
    acc.x *= dn; acc.y *= dn; acc.z *= dn; acc.w *= dn;
    int e0 = g_rowptr[node], e1 = g_rowptr[node + 1];
    for (int e = e0; e < e1; e++) {
        int s = g_csrc[e];
        float ds = g_dis[s];
        float4 v = *(const float4*)&h[s * DIM + lane * 4];
        acc.x += v.x * ds; acc.y += v.y * ds;
        acc.z += v.z * ds; acc.w += v.w * ds;
    }
    float4 b = *(const float4*)&bias[lane * 4];
    float4 r;
    r.x = fmaxf(acc.x * dn + b.x, 0.f);
    r.y = fmaxf(acc.y * dn + b.y, 0.f);
    r.z = fmaxf(acc.z * dn + b.z, 0.f);
    r.w = fmaxf(acc.w * dn + b.w, 0.f);
    *(float4*)&out[node * DIM + lane * 4] = r;
}

// ---------------- GIN aggregation with folded BN affine ----------------
__global__ void k_gin_agg_affine(const float* __restrict__ z, int layer,
                                 float* __restrict__ out) {
    int gt = blockIdx.x * blockDim.x + threadIdx.x;
    int node = gt >> 5;
    int lane = gt & 31;
    if (node >= N_NODES) return;
    float4 acc = *(const float4*)&z[node * DIM + lane * 4];
    int e0 = g_rowptr[node], e1 = g_rowptr[node + 1];
    for (int e = e0; e < e1; e++) {
        int s = g_csrc[e];
        float4 v = *(const float4*)&z[s * DIM + lane * 4];
        acc.x += v.x; acc.y += v.y; acc.z += v.z; acc.w += v.w;
    }
    float4 a = *(const float4*)&g_a[layer * DIM + lane * 4];
    float4 b = *(const float4*)&g_b[layer * DIM + lane * 4];
    float m = (float)(e1 - e0 + 1);
    float4 r;
    r.x = a.x * acc.x + b.x * m;
    r.y = a.y * acc.y + b.y * m;
    r.z = a.z * acc.z + b.z * m;
    r.w = a.w * acc.w + b.w * m;
    *(float4*)&out[node * DIM + lane * 4] = r;
}

// ---------------- GIN layer-0 aggregation (F_IN=78) ----------------
__global__ void k_gin_agg78(const float* __restrict__ x, float* __restrict__ out) {
    int gt = blockIdx.x * blockDim.x + threadIdx.x;
    int node = gt >> 5;
    int lane = gt & 31;
    if (node >= N_NODES) return;
    bool has2 = (lane + 64) < F_IN;
    float a0 = x[node * F_IN + lane];
    float a1 = x[node * F_IN + lane + 32];
    float a2 = has2 ? x[node * F_IN + lane + 64] : 0.f;
    int e0 = g_rowptr[node], e1 = g_rowptr[node + 1];
    for (int e = e0; e < e1; e++) {
        int s = g_csrc[e];
        a0 += x[s * F_IN + lane];
        a1 += x[s * F_IN + lane + 32];
        if (has2) a2 += x[s * F_IN + lane + 64];
    }
    out[node * F_IN + lane] = a0;
    out[node * F_IN + lane + 32] = a1;
    if (has2) out[node * F_IN + lane + 64] = a2;
}

// ---------------- readout ----------------
__global__ void k_readout(float* __restrict__ out) {
    int g = blockIdx.x;
    int c = threadIdx.x;  // 128
    int r0 = g_gstart[g], r1 = g_gstart[g + 1];
    float a1c = g_a[0 * DIM + c], b1c = g_b[0 * DIM + c];
    float a2c = g_a[1 * DIM + c], b2c = g_b[1 * DIM + c];
    float a3c = g_a[2 * DIM + c], b3c = g_b[2 * DIM + c];
    float m1 = -INFINITY, m2 = -INFINITY, m3 = -INFINITY;
    float m4 = -INFINITY, m5 = -INFINITY, m6 = -INFINITY;
    float m7 = -INFINITY, m8 = -INFINITY, m9 = -INFINITY;
    for (int r = r0; r < r1; r++) {
        float a = fmaf(a1c, g_z1[r * DIM + c], b1c);
        float b = fmaf(a2c, g_z2[r * DIM + c], b2c);
        float d = fmaf(a3c, g_z3[r * DIM + c], b3c);
        float e1 = g_g1[r * DIM + c];
        float e2 = g_g2[r * DIM + c];
        m1 = fmaxf(m1, a); m2 = fmaxf(m2, b); m3 = fmaxf(m3, d);
        m4 = fmaxf(m4, a * b * d);
        m5 = fmaxf(m5, a + b + d);
        m6 = fmaxf(m6, e1); m7 = fmaxf(m7, e2);
        m8 = fmaxf(m8, e2 + e1); m9 = fmaxf(m9, e2 * e1);
    }
    float* o = out + (size_t)g * (9 * DIM);
    o[0 * DIM + c] = m1; o[1 * DIM + c] = m2; o[2 * DIM + c] = m3;
    o[3 * DIM + c] = m4; o[4 * DIM + c] = m5; o[5 * DIM + c] = m6;
    o[6 * DIM + c] = m7; o[7 * DIM + c] = m8; o[8 * DIM + c] = m9;
}

// ---------------- launch ----------------
extern "C" void kernel_launch(void* const* d_in, const int* in_sizes, int n_in,
                              void* d_out, int out_size) {
    const float* x = (const float*)d_in[0];
    const int* ei = (const int*)d_in[1];
    const int* src = ei;
    const int* dst = ei + N_EDGES;
    const int* batch = (const int*)d_in[2];
    int base = (n_in >= 18) ? 4 : 3;
    const float* gcn1_W = (const float*)d_in[base + 0];
    const float* gcn1_b = (const float*)d_in[base + 1];
    const float* gcn2_W = (const float*)d_in[base + 2];
    const float* gcn2_b = (const float*)d_in[base + 3];
    const float* gin0_w1 = (const float*)d_in[base + 4];
    const float* gin0_b1 = (const float*)d_in[base + 5];
    const float* gin0_w2 = (const float*)d_in[base + 6];
    const float* gin0_b2 = (const float*)d_in[base + 7];
    const float* gin_w1 = (const float*)d_in[base + 8];
    const float* gin_b1 = (const float*)d_in[base + 9];
    const float* gin_w2 = (const float*)d_in[base + 10];
    const float* gin_b2 = (const float*)d_in[base + 11];
    const float* bn_gamma = (const float*)d_in[base + 12];
    const float* bn_beta = (const float*)d_in[base + 13];
    float* out = (float*)d_out;

    float *t0 = nullptr, *t1 = nullptr, *g1 = nullptr, *g2 = nullptr;
    float *z1 = nullptr, *z2 = nullptr, *z3 = nullptr;
    cudaGetSymbolAddress((void**)&t0, g_t0);
    cudaGetSymbolAddress((void**)&t1, g_t1);
    cudaGetSymbolAddress((void**)&g1, g_g1);
    cudaGetSymbolAddress((void**)&g2, g_g2);
    cudaGetSymbolAddress((void**)&z1, g_z1);
    cudaGetSymbolAddress((void**)&z2, g_z2);
    cudaGetSymbolAddress((void**)&z3, g_z3);

    const int NB_N = (N_NODES + 255) / 256;
    const int NB_E = (N_EDGES + 255) / 256;
    const int NB_GEMM = (N_NODES + TMM - 1) / TMM;
    const int NB_AGG = (N_NODES * 32 + 255) / 256;
    const int SCAN_BLOCKS = (N_NODES + 1023) / 1024;
    const int SMEM_BYTES = SMEM_WORDS * 4;

    static bool attr_done = false;
    if (!attr_done) {
        cudaFuncSetAttribute(k_gemm_mma<F_IN, false, false, -1>, cudaFuncAttributeMaxDynamicSharedMemorySize, SMEM_BYTES);
        cudaFuncSetAttribute(k_gemm_mma<DIM, false, false, -1>, cudaFuncAttributeMaxDynamicSharedMemorySize, SMEM_BYTES);
        cudaFuncSetAttribute(k_gemm_mma<F_IN, true, true, -1>, cudaFuncAttributeMaxDynamicSharedMemorySize, SMEM_BYTES);
        cudaFuncSetAttribute(k_gemm_mma<DIM, true, true, -1>, cudaFuncAttributeMaxDynamicSharedMemorySize, SMEM_BYTES);
        cudaFuncSetAttribute(k_gemm_mma<DIM, true, true, 0>, cudaFuncAttributeMaxDynamicSharedMemorySize, SMEM_BYTES);
        cudaFuncSetAttribute(k_gemm_mma<DIM, true, true, 1>, cudaFuncAttributeMaxDynamicSharedMemorySize, SMEM_BYTES);
        cudaFuncSetAttribute(k_gemm_mma<DIM, true, true, 2>, cudaFuncAttributeMaxDynamicSharedMemorySize, SMEM_BYTES);
        attr_done = true;
    }

    // --- CSR build + degrees + stat zeroing ---
    k_init<<<NB_N, 256>>>();
    k_hist<<<NB_E, 256>>>(dst);
    k_dis<<<NB_N, 256>>>();
    k_scan1<<<SCAN_BLOCKS, 1024>>>();
    k_scan2<<<1, 1>>>(SCAN_BLOCKS);
    k_scan3<<<NB_N, 256>>>();
    k_scatter<<<NB_E, 256>>>(src, dst);
    k_gstart<<<(N_GRAPHS + 1 + 255) / 256, 256>>>(batch);

    // --- GCN1 / GCN2 ---
    k_gemm_mma<F_IN, false, false, -1><<<NB_GEMM, 256, SMEM_BYTES>>>(x, gcn1_W, nullptr, t0);
    k_gcn_agg<<<NB_AGG, 256>>>(t0, gcn1_b, g1);
    k_gemm_mma<DIM, false, false, -1><<<NB_GEMM, 256, SMEM_BYTES>>>(g1, gcn2_W, nullptr, t0);
    k_gcn_agg<<<NB_AGG, 256>>>(t0, gcn2_b, g2);

    // --- GIN layer 0 ---
    k_gin_agg78<<<NB_AGG, 256>>>(x, t1);
    k_gemm_mma<F_IN, true, true, -1><<<NB_GEMM, 256, SMEM_BYTES>>>(t1, gin0_w1, gin0_b1, t0);
    k_gemm_mma<DIM, true, true, 0><<<NB_GEMM, 256, SMEM_BYTES>>>(t0, gin0_w2, gin0_b2, z1);
    k_bn_final<<<1, 128>>>(0, bn_gamma + 0 * DIM, bn_beta + 0 * DIM);

    // --- GIN layer 1 ---
    k_gin_agg_affine<<<NB_AGG, 256>>>(z1, 0, t0);
    k_gemm_mma<DIM, true, true, -1><<<NB_GEMM, 256, SMEM_BYTES>>>(t0, gin_w1 + 0 * DIM * DIM, gin_b1 + 0 * DIM, t1);
    k_gemm_mma<DIM, true, true, 1><<<NB_GEMM, 256, SMEM_BYTES>>>(t1, gin_w2 + 0 * DIM * DIM, gin_b2 + 0 * DIM, z2);
    k_bn_final<<<1, 128>>>(1, bn_gamma + 1 * DIM, bn_beta + 1 * DIM);

    // --- GIN layer 2 ---
    k_gin_agg_affine<<<NB_AGG, 256>>>(z2, 1, t0);
    k_gemm_mma<DIM, true, true, -1><<<NB_GEMM, 256, SMEM_BYTES>>>(t0, gin_w1 + 1 * DIM * DIM, gin_b1 + 1 * DIM, t1);
    k_gemm_mma<DIM, true, true, 2><<<NB_GEMM, 256, SMEM_BYTES>>>(t1, gin_w2 + 1 * DIM * DIM, gin_b2 + 1 * DIM, z3);
    k_bn_final<<<1, 128>>>(2, bn_gamma + 2 * DIM, bn_beta + 2 * DIM);

    // --- readout ---
    k_readout<<<N_GRAPHS, 128>>>(out);
}

// round 7
// speedup vs baseline: 1.1739x; 1.1739x over previous
#include <cuda_runtime.h>
#include <cuda_bf16.h>
#include <math.h>

#define N_NODES 100000
#define N_EDGES 400000
#define N_GRAPHS 2500
#define DIM 128
#define F_IN 78
#define BN_EPS 1e-5f

// ---------------- scratch (device globals; no allocation) ----------------
__device__ float g_t0[N_NODES * DIM];   // branch A temp
__device__ float g_t1[N_NODES * DIM];   // branch B temp
__device__ float g_t2[N_NODES * DIM];   // branch B temp 2
__device__ float g_g1[N_NODES * DIM];
__device__ float g_g2[N_NODES * DIM];
__device__ float g_z1[N_NODES * DIM];   // raw relu(gin) outputs, pre-BN-affine
__device__ float g_z2[N_NODES * DIM];
__device__ float g_z3[N_NODES * DIM];

__device__ int   g_cnt[N_NODES];
__device__ float g_dis[N_NODES];
__device__ int   g_rowptr[N_NODES + 1];
__device__ int   g_cursor[N_NODES];
__device__ int   g_csrc[N_EDGES];
__device__ int   g_blksums[256];
__device__ float g_sum[3 * DIM], g_sumsq[3 * DIM];
__device__ float g_a[3 * DIM], g_b[3 * DIM];   // folded BN affine: h = a*z + b
__device__ int   g_gstart[N_GRAPHS + 1];

// ---------------- f32x2 packed helpers ----------------
__device__ __forceinline__ unsigned long long pack2(float lo, float hi) {
    unsigned long long r;
    asm("mov.b64 %0, {%1, %2};" : "=l"(r) : "f"(lo), "f"(hi));
    return r;
}
__device__ __forceinline__ void unpack2(unsigned long long v, float& lo, float& hi) {
    asm("mov.b64 {%0, %1}, %2;" : "=f"(lo), "=f"(hi) : "l"(v));
}
__device__ __forceinline__ unsigned long long fma2(unsigned long long a,
                                                   unsigned long long b,
                                                   unsigned long long c) {
    unsigned long long d;
    asm("fma.rn.f32x2 %0, %1, %2, %3;" : "=l"(d) : "l"(a), "l"(b), "l"(c));
    return d;
}

// ---------------- init: zero degree counters + BN stats ----------------
__global__ void k_init() {
    int i = blockIdx.x * blockDim.x + threadIdx.x;
    if (i < N_NODES) g_cnt[i] = 0;
    if (i < 3 * DIM) { g_sum[i] = 0.f; g_sumsq[i] = 0.f; }
}

__global__ void k_hist(const int* __restrict__ dst) {
    int e = blockIdx.x * blockDim.x + threadIdx.x;
    if (e < N_EDGES) atomicAdd(&g_cnt[dst[e]], 1);
}

__global__ void k_dis() {
    int i = blockIdx.x * blockDim.x + threadIdx.x;
    if (i < N_NODES) g_dis[i] = rsqrtf((float)(g_cnt[i] + 1));
}

__global__ void k_scan1() {
    __shared__ int s[1024];
    int tid = threadIdx.x;
    int i = blockIdx.x * 1024 + tid;
    int v = (i < N_NODES) ? g_cnt[i] : 0;
    s[tid] = v;
    __syncthreads();
    for (int off = 1; off < 1024; off <<= 1) {
        int t = (tid >= off) ? s[tid - off] : 0;
        __syncthreads();
        s[tid] += t;
        __syncthreads();
    }
    if (i < N_NODES) g_cursor[i] = s[tid];
    if (tid == 1023) g_blksums[blockIdx.x] = s[1023];
}

__global__ void k_scan2(int nblocks) {
    if (threadIdx.x == 0 && blockIdx.x == 0) {
        int run = 0;
        for (int b = 0; b < nblocks; b++) {
            int t = g_blksums[b];
            g_blksums[b] = run;
            run += t;
        }
    }
}

__global__ void k_scan3() {
    int i = blockIdx.x * blockDim.x + threadIdx.x;
    if (i < N_NODES) {
        int val = g_cursor[i] + g_blksums[i >> 10];
        g_rowptr[i + 1] = val;
        g_cursor[i] = val - g_cnt[i];
        if (i == 0) g_rowptr[0] = 0;
    }
}

__global__ void k_scatter(const int* __restrict__ src, const int* __restrict__ dst) {
    int e = blockIdx.x * blockDim.x + threadIdx.x;
    if (e < N_EDGES) {
        int d = dst[e];
        int pos = atomicAdd(&g_cursor[d], 1);
        g_csrc[pos] = src[e];
    }
}

__global__ void k_gstart(const int* __restrict__ batch) {
    int g = blockIdx.x * blockDim.x + threadIdx.x;
    if (g <= N_GRAPHS) {
        int lo = 0, hi = N_NODES;
        while (lo < hi) {
            int mid = (lo + hi) >> 1;
            if (batch[mid] < g) lo = mid + 1; else hi = mid;
        }
        g_gstart[g] = lo;
    }
}

// ---------------- GEMM: C[100000 x 128] = A[. x K] @ W[K x 128] ----------------
// 128x128 tile, 256 threads, 8x8 per thread via packed f32x2 FMA.
#define TM 128
#define KC 32

template <int K, bool BIAS, bool RELU, int STATS>
__global__ void __launch_bounds__(256) k_gemm(const float* __restrict__ A,
                                              const float* __restrict__ W,
                                              const float* __restrict__ bias,
                                              float* __restrict__ C) {
    __shared__ float As[KC][TM + 4];       // row stride 132 floats (16B aligned)
    __shared__ float Bs[KC][DIM];
    __shared__ float Sred[(STATS >= 0) ? 16 : 1][DIM];

    const int tid = threadIdx.x;
    const int tx = tid & 15;   // 8 cols: tx*8 .. tx*8+7
    const int ty = tid >> 4;   // 8 rows: ty*4..+3 and 64+ty*4..+3
    const int row0 = blockIdx.x * TM;

    unsigned long long acc[8][4];
#pragma unroll
    for (int i = 0; i < 8; i++)
#pragma unroll
        for (int j = 0; j < 4; j++) acc[i][j] = 0ull;

    constexpr int KSTEPS = (K + KC - 1) / KC;
    for (int s = 0; s < KSTEPS; s++) {
        const int kk = s * KC;
        if constexpr (K % KC == 0) {
#pragma unroll
            for (int t = 0; t < 4; t++) {
                int idx = tid + t * 256;       // 1024 float4
                int r = idx >> 3, c4 = idx & 7;
                float4 v = make_float4(0.f, 0.f, 0.f, 0.f);
                int grow = row0 + r;
                if (grow < N_NODES) v = *(const float4*)&A[grow * K + kk + c4 * 4];
                As[c4 * 4 + 0][r] = v.x;
                As[c4 * 4 + 1][r] = v.y;
                As[c4 * 4 + 2][r] = v.z;
                As[c4 * 4 + 3][r] = v.w;
            }
        } else {
#pragma unroll
            for (int t = 0; t < 16; t++) {
                int idx = tid + t * 256;       // 4096 scalars
                int r = idx >> 5, c = idx & 31;
                int grow = row0 + r, gcol = kk + c;
                float v = 0.f;
                if (grow < N_NODES && gcol < K) v = A[grow * K + gcol];
                As[c][r] = v;
            }
        }
#pragma unroll
        for (int t = 0; t < 4; t++) {
            int idx = tid + t * 256;           // 1024 float4
            int k = idx >> 5, c4 = idx & 31;
            int gk = kk + k;
            float4 v = make_float4(0.f, 0.f, 0.f, 0.f);
            if (gk < K) v = *(const float4*)&W[gk * DIM + c4 * 4];
            *(float4*)&Bs[k][c4 * 4] = v;
        }
        __syncthreads();

#pragma unroll 8
        for (int k = 0; k < KC; k++) {
            float4 a0 = *(const float4*)&As[k][ty * 4];
            float4 a1 = *(const float4*)&As[k][64 + ty * 4];
            ulonglong2 bq0 = *(const ulonglong2*)&Bs[k][tx * 8];
            ulonglong2 bq1 = *(const ulonglong2*)&Bs[k][tx * 8 + 4];
            unsigned long long B[4] = {bq0.x, bq0.y, bq1.x, bq1.y};
            unsigned long long Ap[8];
            Ap[0] = pack2(a0.x, a0.x); Ap[1] = pack2(a0.y, a0.y);
            Ap[2] = pack2(a0.z, a0.z); Ap[3] = pack2(a0.w, a0.w);
            Ap[4] = pack2(a1.x, a1.x); Ap[5] = pack2(a1.y, a1.y);
            Ap[6] = pack2(a1.z, a1.z); Ap[7] = pack2(a1.w, a1.w);
#pragma unroll
            for (int i = 0; i < 8; i++)
#pragma unroll
                for (int j = 0; j < 4; j++)
                    acc[i][j] = fma2(Ap[i], B[j], acc[i][j]);
        }
        __syncthreads();
    }

    float bv[8];
#pragma unroll
    for (int j = 0; j < 8; j++) bv[j] = BIAS ? bias[tx * 8 + j] : 0.f;

    float cs[8], cq[8];
#pragma unroll
    for (int j = 0; j < 8; j++) { cs[j] = 0.f; cq[j] = 0.f; }

#pragma unroll
    for (int i = 0; i < 8; i++) {
        int row = row0 + ((i < 4) ? (ty * 4 + i) : (64 + ty * 4 + i - 4));
        float v[8];
#pragma unroll
        for (int j = 0; j < 4; j++) unpack2(acc[i][j], v[2 * j], v[2 * j + 1]);
#pragma unroll
        for (int j = 0; j < 8; j++) {
            v[j] += bv[j];
            if (RELU) v[j] = fmaxf(v[j], 0.f);
        }
        if (row < N_NODES) {
            float4 o0 = make_float4(v[0], v[1], v[2], v[3]);
            float4 o1 = make_float4(v[4], v[5], v[6], v[7]);
            *(float4*)&C[row * DIM + tx * 8] = o0;
            *(float4*)&C[row * DIM + tx * 8 + 4] = o1;
            if (STATS >= 0) {
#pragma unroll
                for (int j = 0; j < 8; j++) { cs[j] += v[j]; cq[j] += v[j] * v[j]; }
            }
        }
    }

    if constexpr (STATS >= 0) {
#pragma unroll
        for (int j = 0; j < 8; j++) Sred[ty][tx * 8 + j] = cs[j];
        __syncthreads();
        if (tid < DIM) {
            float t = 0.f;
#pragma unroll
            for (int r = 0; r < 16; r++) t += Sred[r][tid];
            atomicAdd(&g_sum[STATS * DIM + tid], t);
        }
        __syncthreads();
#pragma unroll
        for (int j = 0; j < 8; j++) Sred[ty][tx * 8 + j] = cq[j];
        __syncthreads();
        if (tid < DIM) {
            float t = 0.f;
#pragma unroll
            for (int r = 0; r < 16; r++) t += Sred[r][tid];
            atomicAdd(&g_sumsq[STATS * DIM + tid], t);
        }
    }
}

// ---------------- BN finalize: fold into affine h = a*z + b ----------------
__global__ void k_bn_final(int layer, const float* __restrict__ gamma,
                           const float* __restrict__ beta) {
    int c = threadIdx.x;
    if (c < DIM) {
        float mu = g_sum[layer * DIM + c] * (1.f / N_NODES);
        float var = g_sumsq[layer * DIM + c] * (1.f / N_NODES) - mu * mu;
        float istd = rsqrtf(var + BN_EPS);
        float a = istd * gamma[c];
        g_a[layer * DIM + c] = a;
        g_b[layer * DIM + c] = beta[c] - mu * a;
    }
}

// ---------------- GCN aggregation ----------------
__global__ void k_gcn_agg(const float* __restrict__ h, const float* __restrict__ bias,
                          float* __restrict__ out) {
    int gt = blockIdx.x * blockDim.x + threadIdx.x;
    int node = gt >> 5;
    int lane = gt & 31;
    if (node >= N_NODES) return;
    float dn = g_dis[node];
    float4 acc = *(const float4*)&h[node * DIM + lane * 4];
    acc.x *= dn; acc.y *= dn; acc.z *= dn; acc.w *= dn;
    int e0 = g_rowptr[node], e1 = g_rowptr[node + 1];
    for (int e = e0; e < e1; e++) {
        int s = g_csrc[e];
        float ds = g_dis[s];
        float4 v = *(const float4*)&h[s * DIM + lane * 4];
        acc.x += v.x * ds; acc.y += v.y * ds;
        acc.z += v.z * ds; acc.w += v.w * ds;
    }
    float4 b = *(const float4*)&bias[lane * 4];
    float4 r;
    r.x = fmaxf(acc.x * dn + b.x, 0.f);
    r.y = fmaxf(acc.y * dn + b.y, 0.f);
    r.z = fmaxf(acc.z * dn + b.z, 0.f);
    r.w = fmaxf(acc.w * dn + b.w, 0.f);
    *(float4*)&out[node * DIM + lane * 4] = r;
}

// ---------------- GIN aggregation with folded BN affine ----------------
__global__ void k_gin_agg_affine(const float* __restrict__ z, int layer,
                                 float* __restrict__ out) {
    int gt = blockIdx.x * blockDim.x + threadIdx.x;
    int node = gt >> 5;
    int lane = gt & 31;
    if (node >= N_NODES) return;
    float4 acc = *(const float4*)&z[node * DIM + lane * 4];
    int e0 = g_rowptr[node], e1 = g_rowptr[node + 1];
    for (int e = e0; e < e1; e++) {
        int s = g_csrc[e];
        float4 v = *(const float4*)&z[s * DIM + lane * 4];
        acc.x += v.x; acc.y += v.y; acc.z += v.z; acc.w += v.w;
    }
    float4 a = *(const float4*)&g_a[layer * DIM + lane * 4];
    float4 b = *(const float4*)&g_b[layer * DIM + lane * 4];
    float m = (float)(e1 - e0 + 1);
    float4 r;
    r.x = a.x * acc.x + b.x * m;
    r.y = a.y * acc.y + b.y * m;
    r.z = a.z * acc.z + b.z * m;
    r.w = a.w * acc.w + b.w * m;
    *(float4*)&out[node * DIM + lane * 4] = r;
}

// ---------------- GIN layer-0 aggregation (F_IN=78) ----------------
__global__ void k_gin_agg78(const float* __restrict__ x, float* __restrict__ out) {
    int gt = blockIdx.x * blockDim.x + threadIdx.x;
    int node = gt >> 5;
    int lane = gt & 31;
    if (node >= N_NODES) return;
    bool has2 = (lane + 64) < F_IN;
    float a0 = x[node * F_IN + lane];
    float a1 = x[node * F_IN + lane + 32];
    float a2 = has2 ? x[node * F_IN + lane + 64] : 0.f;
    int e0 = g_rowptr[node], e1 = g_rowptr[node + 1];
    for (int e = e0; e < e1; e++) {
        int s = g_csrc[e];
        a0 += x[s * F_IN + lane];
        a1 += x[s * F_IN + lane + 32];
        if (has2) a2 += x[s * F_IN + lane + 64];
    }
    out[node * F_IN + lane] = a0;
    out[node * F_IN + lane + 32] = a1;
    if (has2) out[node * F_IN + lane + 64] = a2;
}

// ---------------- readout ----------------
__global__ void k_readout(float* __restrict__ out) {
    int g = blockIdx.x;
    int c = threadIdx.x;  // 128
    int r0 = g_gstart[g], r1 = g_gstart[g + 1];
    float a1c = g_a[0 * DIM + c], b1c = g_b[0 * DIM + c];
    float a2c = g_a[1 * DIM + c], b2c = g_b[1 * DIM + c];
    float a3c = g_a[2 * DIM + c], b3c = g_b[2 * DIM + c];
    float m1 = -INFINITY, m2 = -INFINITY, m3 = -INFINITY;
    float m4 = -INFINITY, m5 = -INFINITY, m6 = -INFINITY;
    float m7 = -INFINITY, m8 = -INFINITY, m9 = -INFINITY;
    for (int r = r0; r < r1; r++) {
        float a = fmaf(a1c, g_z1[r * DIM + c], b1c);
        float b = fmaf(a2c, g_z2[r * DIM + c], b2c);
        float d = fmaf(a3c, g_z3[r * DIM + c], b3c);
        float e1 = g_g1[r * DIM + c];
        float e2 = g_g2[r * DIM + c];
        m1 = fmaxf(m1, a); m2 = fmaxf(m2, b); m3 = fmaxf(m3, d);
        m4 = fmaxf(m4, a * b * d);
        m5 = fmaxf(m5, a + b + d);
        m6 = fmaxf(m6, e1); m7 = fmaxf(m7, e2);
        m8 = fmaxf(m8, e2 + e1); m9 = fmaxf(m9, e2 * e1);
    }
    float* o = out + (size_t)g * (9 * DIM);
    o[0 * DIM + c] = m1; o[1 * DIM + c] = m2; o[2 * DIM + c] = m3;
    o[3 * DIM + c] = m4; o[4 * DIM + c] = m5; o[5 * DIM + c] = m6;
    o[6 * DIM + c] = m7; o[7 * DIM + c] = m8; o[8 * DIM + c] = m9;
}

// ---------------- launch ----------------
extern "C" void kernel_launch(void* const* d_in, const int* in_sizes, int n_in,
                              void* d_out, int out_size) {
    const float* x = (const float*)d_in[0];
    const int* ei = (const int*)d_in[1];
    const int* src = ei;
    const int* dst = ei + N_EDGES;
    const int* batch = (const int*)d_in[2];
    int base = (n_in >= 18) ? 4 : 3;
    const float* gcn1_W = (const float*)d_in[base + 0];
    const float* gcn1_b = (const float*)d_in[base + 1];
    const float* gcn2_W = (const float*)d_in[base + 2];
    const float* gcn2_b = (const float*)d_in[base + 3];
    const float* gin0_w1 = (const float*)d_in[base + 4];
    const float* gin0_b1 = (const float*)d_in[base + 5];
    const float* gin0_w2 = (const float*)d_in[base + 6];
    const float* gin0_b2 = (const float*)d_in[base + 7];
    const float* gin_w1 = (const float*)d_in[base + 8];
    const float* gin_b1 = (const float*)d_in[base + 9];
    const float* gin_w2 = (const float*)d_in[base + 10];
    const float* gin_b2 = (const float*)d_in[base + 11];
    const float* bn_gamma = (const float*)d_in[base + 12];
    const float* bn_beta = (const float*)d_in[base + 13];
    float* out = (float*)d_out;

    float *t0 = nullptr, *t1 = nullptr, *t2 = nullptr;
    float *g1 = nullptr, *g2 = nullptr;
    float *z1 = nullptr, *z2 = nullptr, *z3 = nullptr;
    cudaGetSymbolAddress((void**)&t0, g_t0);
    cudaGetSymbolAddress((void**)&t1, g_t1);
    cudaGetSymbolAddress((void**)&t2, g_t2);
    cudaGetSymbolAddress((void**)&g1, g_g1);
    cudaGetSymbolAddress((void**)&g2, g_g2);
    cudaGetSymbolAddress((void**)&z1, g_z1);
    cudaGetSymbolAddress((void**)&z2, g_z2);
    cudaGetSymbolAddress((void**)&z3, g_z3);

    // persistent streams/events (host-side resources only; created once)
    static cudaStream_t sA = nullptr, sB = nullptr;
    static cudaEvent_t evStart = nullptr, evCSR = nullptr, evA = nullptr, evB = nullptr;
    if (!sA) {
        cudaStreamCreateWithFlags(&sA, cudaStreamNonBlocking);
        cudaStreamCreateWithFlags(&sB, cudaStreamNonBlocking);
        cudaEventCreateWithFlags(&evStart, cudaEventDisableTiming);
        cudaEventCreateWithFlags(&evCSR, cudaEventDisableTiming);
        cudaEventCreateWithFlags(&evA, cudaEventDisableTiming);
        cudaEventCreateWithFlags(&evB, cudaEventDisableTiming);
    }

    const int NB_N = (N_NODES + 255) / 256;
    const int NB_E = (N_EDGES + 255) / 256;
    const int NB_GEMM = (N_NODES + TM - 1) / TM;
    const int NB_AGG = (N_NODES * 32 + 255) / 256;
    const int SCAN_BLOCKS = (N_NODES + 1023) / 1024;

    // ---- fork point: both branches may start GEMMs that don't need CSR ----
    cudaEventRecord(evStart, 0);
    cudaStreamWaitEvent(sA, evStart, 0);
    cudaStreamWaitEvent(sB, evStart, 0);

    // ---- stream 0: CSR build + degrees + stat zeroing + graph starts ----
    k_init<<<NB_N, 256>>>();
    k_hist<<<NB_E, 256>>>(dst);
    k_dis<<<NB_N, 256>>>();
    k_scan1<<<SCAN_BLOCKS, 1024>>>();
    k_scan2<<<1, 1>>>(SCAN_BLOCKS);
    k_scan3<<<NB_N, 256>>>();
    k_scatter<<<NB_E, 256>>>(src, dst);
    cudaEventRecord(evCSR, 0);
    k_gstart<<<(N_GRAPHS + 1 + 255) / 256, 256>>>(batch);

    // ---- branch A (stream sA): GCN chain ----
    // GCN1 GEMM needs only x/W — runs concurrently with CSR build.
    k_gemm<F_IN, false, false, -1><<<NB_GEMM, 256, 0, sA>>>(x, gcn1_W, nullptr, t0);
    cudaStreamWaitEvent(sA, evCSR, 0);
    k_gcn_agg<<<NB_AGG, 256, 0, sA>>>(t0, gcn1_b, g1);
    k_gemm<DIM, false, false, -1><<<NB_GEMM, 256, 0, sA>>>(g1, gcn2_W, nullptr, t0);
    k_gcn_agg<<<NB_AGG, 256, 0, sA>>>(t0, gcn2_b, g2);
    cudaEventRecord(evA, sA);

    // ---- branch B (stream sB): GIN chain ----
    cudaStreamWaitEvent(sB, evCSR, 0);
    k_gin_agg78<<<NB_AGG, 256, 0, sB>>>(x, t1);
    k_gemm<F_IN, true, true, -1><<<NB_GEMM, 256, 0, sB>>>(t1, gin0_w1, gin0_b1, t2);
    k_gemm<DIM, true, true, 0><<<NB_GEMM, 256, 0, sB>>>(t2, gin0_w2, gin0_b2, z1);
    k_bn_final<<<1, 128, 0, sB>>>(0, bn_gamma + 0 * DIM, bn_beta + 0 * DIM);

    k_gin_agg_affine<<<NB_AGG, 256, 0, sB>>>(z1, 0, t1);
    k_gemm<DIM, true, true, -1><<<NB_GEMM, 256, 0, sB>>>(t1, gin_w1 + 0 * DIM * DIM, gin_b1 + 0 * DIM, t2);
    k_gemm<DIM, true, true, 1><<<NB_GEMM, 256, 0, sB>>>(t2, gin_w2 + 0 * DIM * DIM, gin_b2 + 0 * DIM, z2);
    k_bn_final<<<1, 128, 0, sB>>>(1, bn_gamma + 1 * DIM, bn_beta + 1 * DIM);

    k_gin_agg_affine<<<NB_AGG, 256, 0, sB>>>(z2, 1, t1);
    k_gemm<DIM, true, true, -1><<<NB_GEMM, 256, 0, sB>>>(t1, gin_w1 + 1 * DIM * DIM, gin_b1 + 1 * DIM, t2);
    k_gemm<DIM, true, true, 2><<<NB_GEMM, 256, 0, sB>>>(t2, gin_w2 + 1 * DIM * DIM, gin_b2 + 1 * DIM, z3);
    k_bn_final<<<1, 128, 0, sB>>>(2, bn_gamma + 2 * DIM, bn_beta + 2 * DIM);
    cudaEventRecord(evB, sB);

    // ---- join + readout on stream 0 ----
    cudaStreamWaitEvent(0, evA, 0);
    cudaStreamWaitEvent(0, evB, 0);
    k_readout<<<N_GRAPHS, 128>>>(out);
}